// round 8
// baseline (speedup 1.0000x reference)
#include <cuda_runtime.h>
#include <cuda_fp16.h>
#include <cstdint>

#define DI __device__ __forceinline__

// ---------------- problem constants ----------------
constexpr int B_   = 16;
constexpr int C_   = 384;
constexpr int H_   = 56;
constexpr int W_   = 56;
constexpr int HW   = H_ * W_;          // 3136
constexpr int M_   = B_ * HW;          // 50176 (pixels)
constexpr int K0   = 2 * C_;           // 768
constexpr int NOUT = 384;
constexpr int K2J  = 192;              // xj k2 rows (384 xj channels / 2)

// ---------------- device scratch ----------------
// Xp: xj half only. word (r, m) = {fp16 xj[2r](m), fp16 xj[2r+1](m)}, [b][r][hw]
__device__ __align__(256) uint32_t g_Xp[(size_t)B_ * K2J * HW];     // 38.5 MB
__device__ __align__(256) __half   g_Wh[NOUT * K0];                 // fp16 W [n][k]
__device__ __align__(256) float    g_acc[(size_t)M_ * NOUT];        // 77 MB partial

// ---------------- PTX helpers ----------------
DI uint32_t smem_u32(const void* p) {
    uint32_t a;
    asm("{ .reg .u64 t; cvta.to.shared.u64 t, %1; cvt.u32.u64 %0, t; }"
        : "=r"(a) : "l"(p));
    return a;
}

#define CP_ASYNC16(smem, gptr) \
    asm volatile("cp.async.cg.shared.global [%0], [%1], 16;" :: "r"(smem), "l"(gptr))
#define CP_COMMIT() asm volatile("cp.async.commit_group;")
#define CP_WAIT1()  asm volatile("cp.async.wait_group 1;")
#define CP_WAIT0()  asm volatile("cp.async.wait_group 0;")

DI void ldsm_x4(uint32_t* r, uint32_t addr) {
    asm volatile("ldmatrix.sync.aligned.m8n8.x4.shared.b16 {%0,%1,%2,%3}, [%4];"
                 : "=r"(r[0]), "=r"(r[1]), "=r"(r[2]), "=r"(r[3]) : "r"(addr));
}

DI uint32_t lds_u32(uint32_t addr) {
    uint32_t v;
    asm volatile("ld.shared.b32 %0, [%1];" : "=r"(v) : "r"(addr));
    return v;
}

#define STS128(addr, v0, v1, v2, v3) \
    asm volatile("st.shared.v4.b32 [%0], {%1, %2, %3, %4};" \
        :: "r"(addr), "r"(v0), "r"(v1), "r"(v2), "r"(v3) : "memory")

// D[16 n][8 m] += A[16 n][16 k](f16) * B[16 k][8 m](f16), f32 accum
DI void mma_f16(float* d, const uint32_t* a, uint32_t b0, uint32_t b1) {
    asm volatile(
        "mma.sync.aligned.m16n8k16.row.col.f32.f16.f16.f32 "
        "{%0,%1,%2,%3},{%4,%5,%6,%7},{%8,%9},{%0,%1,%2,%3};"
        : "+f"(d[0]), "+f"(d[1]), "+f"(d[2]), "+f"(d[3])
        : "r"(a[0]), "r"(a[1]), "r"(a[2]), "r"(a[3]), "r"(b0), "r"(b1));
}

DI uint32_t pack_h2(float a, float b) {
    __half2 h = __halves2half2(__float2half_rn(a), __float2half_rn(b));
    return *reinterpret_cast<uint32_t*>(&h);
}

DI __half2 u2h(uint32_t u) { return *reinterpret_cast<__half2*>(&u); }
DI uint32_t h2u(__half2 h) { return *reinterpret_cast<uint32_t*>(&h); }

// ---------------- kernel 1: W -> fp16 [n][k] ----------------
__global__ void whalf_kernel(const float* __restrict__ w) {
    const int i = blockIdx.x * blockDim.x + threadIdx.x;
    if (i < NOUT * K0) g_Wh[i] = __float2half_rn(w[i]);
}

// ---------------- kernel 2: xjpack (xj only, half2 tile) ----------------
constexpr int TSTR = 120;
constexpr int XJ_SMEM = 118 * TSTR * 4;             // 56640 B

__global__ void __launch_bounds__(448, 3) xjpack_kernel(const float* __restrict__ x) {
    extern __shared__ uint32_t t[];

    const int c2 = blockIdx.x % (C_ / 2);
    const int b  = blockIdx.x / (C_ / 2);
    const float* src0 = x + ((size_t)b * C_ + 2 * c2    ) * HW;
    const float* src1 = x + ((size_t)b * C_ + 2 * c2 + 1) * HW;

    const int w  = threadIdx.x;                 // 0..63 (>=56 idle)
    const int ty = threadIdx.y;                 // 0..6
    const int hb = ty * 8;

    if (w < W_) {
#pragma unroll
        for (int j = 0; j < 8; j++)
            t[(31 + hb + j) * TSTR + 31 + w] =
                pack_h2(src0[(hb + j) * W_ + w], src1[(hb + j) * W_ + w]);
    }
    __syncthreads();

    if (w < W_) {
#pragma unroll
        for (int r = ty; r < 31; r += 7) {
            t[r * TSTR + 31 + w]        = t[(r + 56) * TSTR + 31 + w];
            t[(r + 87) * TSTR + 31 + w] = t[(r + 31) * TSTR + 31 + w];
        }
    }
    if (w < 31) {
#pragma unroll
        for (int r = 31 + ty; r < 87; r += 7) {
            t[r * TSTR + w]      = t[r * TSTR + w + 56];
            t[r * TSTR + 87 + w] = t[r * TSTR + 31 + w];
        }
    }
    __syncthreads();

    if (w >= W_) return;

    const uint32_t* bp = &t[(31 + hb) * TSTR + 31 + w];
    uint32_t* dj = g_Xp + ((size_t)b * K2J + c2) * HW + hb * W_ + w;
    const __half2 zero = __half2half2(__float2half(0.f));

#pragma unroll 2
    for (int j = 0; j < 8; j++) {
        const uint32_t* p = bp + j * TSTR;
        const __half2 v = u2h(p[0]);

        __half2 m = __hmin2(u2h(p[-1 * TSTR]),  u2h(p[1 * TSTR]));
        m = __hmin2(m, __hmin2(u2h(p[-3 * TSTR]),  u2h(p[3 * TSTR])));
        m = __hmin2(m, __hmin2(u2h(p[-7 * TSTR]),  u2h(p[7 * TSTR])));
        m = __hmin2(m, __hmin2(u2h(p[-15 * TSTR]), u2h(p[15 * TSTR])));
        m = __hmin2(m, __hmin2(u2h(p[-31 * TSTR]), u2h(p[31 * TSTR])));
        m = __hmin2(m, __hmin2(u2h(p[-1]),  u2h(p[1])));
        m = __hmin2(m, __hmin2(u2h(p[-3]),  u2h(p[3])));
        m = __hmin2(m, __hmin2(u2h(p[-7]),  u2h(p[7])));
        m = __hmin2(m, __hmin2(u2h(p[-15]), u2h(p[15])));
        m = __hmin2(m, __hmin2(u2h(p[-31]), u2h(p[31])));

        dj[j * W_] = h2u(__hmax2(__hsub2(v, m), zero));
    }
}

// ---------------- shared GEMM geometry ----------------
constexpr int MT  = 128;
constexpr int NT  = 128;
constexpr int KT  = 32;          // k per chunk
constexpr int NCHH = (K0 / 2) / KT;   // 12 chunks per half
constexpr int SXS = 136;         // sX row stride (words)
constexpr int SWSH = 40;         // sW row stride (halfs)
constexpr int SX_STAGE_W = 16 * SXS;          // 2176 words
constexpr int SW_STAGE_H = NT * SWSH;         // 5120 halfs
constexpr int SMEM_XJ = 2 * SX_STAGE_W * 4 + 2 * SW_STAGE_H * 2;   // 37888
constexpr int SMEM_X  = SX_STAGE_W * 4 + 2 * SW_STAGE_H * 2;       // 29184

// ---------------- kernel 3: gemm_x (x half of K, fp32 source) -------------
// Stages x via LDG.128 + cvt + STS (no xjpack dependency). Raw acc -> g_acc.
__global__ void __launch_bounds__(256, 2) gemm_x_kernel(const float* __restrict__ x)
{
    extern __shared__ uint32_t smw[];
    uint32_t* sX = smw;                              // [16][SXS]
    __half*   sW = (__half*)(smw + SX_STAGE_W);      // [2][NT][SWSH]

    const int tid  = threadIdx.x;
    const int lane = tid & 31;
    const int wid  = tid >> 5;
    const int wn   = wid & 1;
    const int wp   = wid >> 1;
    const int n0   = blockIdx.x * NT;
    const int m0   = blockIdx.y * MT;

    const uint32_t sxB = smem_u32(sX);
    const uint32_t swB = smem_u32(sW);

    // per-thread x staging coords (2 units of 16B)
    int   uk2[2], umv[2];
    const float* up0[2];
    const float* up1[2];
#pragma unroll
    for (int u = 0; u < 2; u++) {
        const int idx = tid + 256 * u;
        uk2[u] = idx >> 5;
        umv[u] = idx & 31;
        const int m = m0 + 4 * umv[u];
        const unsigned b  = (unsigned)m / HW;
        const unsigned hw = (unsigned)m - b * HW;
        up0[u] = x + ((size_t)b * C_ + 2 * uk2[u]    ) * HW + hw;
        up1[u] = x + ((size_t)b * C_ + 2 * uk2[u] + 1) * HW + hw;
    }

    auto cp_w = [&](int ch, int st) {
        const uint32_t wb = swB + (uint32_t)st * SW_STAGE_H * 2;
#pragma unroll
        for (int i = 0; i < 2; i++) {
            const int idx = tid + 256 * i;
            const int n   = idx >> 2;
            const int kv  = idx & 3;
            const __half* src = g_Wh + (size_t)(n0 + n) * K0 + ch * KT + 8 * kv;
            CP_ASYNC16(wb + (uint32_t)(n * SWSH + 8 * kv) * 2, src);
        }
    };

    float4 ra[2], rb[2];
    auto ldg_x = [&]() {
#pragma unroll
        for (int u = 0; u < 2; u++) {
            ra[u] = *reinterpret_cast<const float4*>(up0[u]);
            rb[u] = *reinterpret_cast<const float4*>(up1[u]);
            up0[u] += (size_t)32 * HW;     // +16 k2 rows = +32 channels
            up1[u] += (size_t)32 * HW;
        }
    };
    auto sts_x = [&]() {
#pragma unroll
        for (int u = 0; u < 2; u++) {
            const uint32_t a = sxB + (uint32_t)(uk2[u] * SXS + 4 * umv[u]) * 4;
            STS128(a, pack_h2(ra[u].x, rb[u].x), pack_h2(ra[u].y, rb[u].y),
                      pack_h2(ra[u].z, rb[u].z), pack_h2(ra[u].w, rb[u].w));
        }
    };

    float acc[4][4][4];
#pragma unroll
    for (int a = 0; a < 4; a++)
#pragma unroll
        for (int j = 0; j < 4; j++)
#pragma unroll
            for (int q = 0; q < 4; q++) acc[a][j][q] = 0.f;

    ldg_x();
    cp_w(0, 0);
    CP_COMMIT();

    const int jrow = (lane & 7) + ((lane >> 3) & 1) * 8;
    const int kcol = (lane >> 4) * 8;

#pragma unroll 1
    for (int ch = 0; ch < NCHH; ch++) {
        const int st = ch & 1;
        CP_WAIT0();                        // W(ch) ready
        sts_x();
        __syncthreads();                   // stage complete

        if (ch + 1 < NCHH) {
            ldg_x();                       // overlaps mma below
            cp_w(ch + 1, st ^ 1);
            CP_COMMIT();
        }

        const uint32_t wb = swB + (uint32_t)st * SW_STAGE_H * 2;
#pragma unroll
        for (int ks = 0; ks < 2; ks++) {
            uint32_t afr[4][4];
#pragma unroll
            for (int nf = 0; nf < 4; nf++) {
                const int row = wn * 64 + nf * 16 + jrow;
                ldsm_x4(afr[nf], wb + (uint32_t)(row * SWSH + ks * 16 + kcol) * 2);
            }
            const uint32_t bbase = sxB + (uint32_t)((ks * 8 + (lane & 3)) * SXS
                                                    + wp * 32 + (lane >> 2)) * 4;
#pragma unroll
            for (int j = 0; j < 4; j++) {
                const uint32_t a0 = bbase + (uint32_t)(j * 8) * 4;
                const uint32_t b0 = lds_u32(a0);
                const uint32_t b1 = lds_u32(a0 + (uint32_t)(4 * SXS) * 4);
                mma_f16(acc[0][j], afr[0], b0, b1);
                mma_f16(acc[1][j], afr[1], b0, b1);
                mma_f16(acc[2][j], afr[2], b0, b1);
                mma_f16(acc[3][j], afr[3], b0, b1);
            }
        }
        __syncthreads();                   // sX consumed before next STS
    }

    // store raw partial sums
#pragma unroll
    for (int nf = 0; nf < 4; nf++) {
#pragma unroll
        for (int half = 0; half < 2; half++) {
            const int n = n0 + wn * 64 + nf * 16 + (lane >> 2) + half * 8;
#pragma unroll
            for (int j = 0; j < 4; j++) {
                const int m = m0 + wp * 32 + j * 8 + 2 * (lane & 3);
                const unsigned b  = (unsigned)m / HW;
                const unsigned hw = (unsigned)m - b * HW;
                *reinterpret_cast<float2*>(
                    g_acc + ((size_t)b * NOUT + n) * HW + hw) =
                    make_float2(acc[nf][j][half * 2], acc[nf][j][half * 2 + 1]);
            }
        }
    }
}

// ---------------- kernel 4: gemm_xj (xj half) + scratch + BN + GELU --------
__global__ void __launch_bounds__(256, 2) gemm_xj_kernel(
    const float* __restrict__ conv_b,
    const float* __restrict__ bn_scale, const float* __restrict__ bn_bias,
    const float* __restrict__ bn_mean,  const float* __restrict__ bn_var,
    float* __restrict__ out)
{
    extern __shared__ uint32_t smw[];
    uint32_t* sX = smw;                              // [2][16][SXS]
    __half*   sW = (__half*)(smw + 2 * SX_STAGE_W);  // [2][NT][SWSH]
    __shared__ float s_s[NT], s_t[NT];

    const int tid  = threadIdx.x;
    const int lane = tid & 31;
    const int wid  = tid >> 5;
    const int wn   = wid & 1;
    const int wp   = wid >> 1;
    const int n0   = blockIdx.x * NT;
    const int m0   = blockIdx.y * MT;

    if (tid < NT) {
        const int n = n0 + tid;
        const float inv = rsqrtf(bn_var[n] + 1e-5f);
        const float s = inv * bn_scale[n];
        s_s[tid] = s;
        s_t[tid] = (conv_b[n] - bn_mean[n]) * s + bn_bias[n];
    }

    const uint32_t sxB = smem_u32(sX);
    const uint32_t swB = smem_u32(sW);

    auto load_chunk = [&](int ch, int st) {
        const int kc2 = ch * (KT / 2);
        const uint32_t xb = sxB + (uint32_t)st * SX_STAGE_W * 4;
        const uint32_t wb = swB + (uint32_t)st * SW_STAGE_H * 2;
#pragma unroll
        for (int i = 0; i < 2; i++) {
            const int idx = tid + 256 * i;
            const int k2  = idx >> 5;
            const int mv  = idx & 31;
            const int m   = m0 + 4 * mv;
            const unsigned b  = (unsigned)m / HW;
            const unsigned hw = (unsigned)m - b * HW;
            const uint32_t* src = g_Xp + ((size_t)b * K2J + kc2 + k2) * HW + hw;
            CP_ASYNC16(xb + (uint32_t)(k2 * SXS + 4 * mv) * 4, src);
        }
#pragma unroll
        for (int i = 0; i < 2; i++) {
            const int idx = tid + 256 * i;
            const int n   = idx >> 2;
            const int kv  = idx & 3;
            const __half* src = g_Wh + (size_t)(n0 + n) * K0 + 384 + ch * KT + 8 * kv;
            CP_ASYNC16(wb + (uint32_t)(n * SWSH + 8 * kv) * 2, src);
        }
    };

    float acc[4][4][4];
#pragma unroll
    for (int a = 0; a < 4; a++)
#pragma unroll
        for (int j = 0; j < 4; j++)
#pragma unroll
            for (int q = 0; q < 4; q++) acc[a][j][q] = 0.f;

    load_chunk(0, 0);
    CP_COMMIT();

    const int jrow = (lane & 7) + ((lane >> 3) & 1) * 8;
    const int kcol = (lane >> 4) * 8;

#pragma unroll 1
    for (int ch = 0; ch < NCHH; ch++) {
        if (ch + 1 < NCHH) {
            load_chunk(ch + 1, (ch + 1) & 1);
            CP_COMMIT();
            CP_WAIT1();
        } else {
            CP_WAIT0();
        }
        __syncthreads();

        const int st = ch & 1;
        const uint32_t xb = sxB + (uint32_t)st * SX_STAGE_W * 4;
        const uint32_t wb = swB + (uint32_t)st * SW_STAGE_H * 2;

#pragma unroll
        for (int ks = 0; ks < 2; ks++) {
            uint32_t afr[4][4];
#pragma unroll
            for (int nf = 0; nf < 4; nf++) {
                const int row = wn * 64 + nf * 16 + jrow;
                ldsm_x4(afr[nf], wb + (uint32_t)(row * SWSH + ks * 16 + kcol) * 2);
            }
            const uint32_t bbase = xb + (uint32_t)((ks * 8 + (lane & 3)) * SXS
                                                   + wp * 32 + (lane >> 2)) * 4;
#pragma unroll
            for (int j = 0; j < 4; j++) {
                const uint32_t a0 = bbase + (uint32_t)(j * 8) * 4;
                const uint32_t b0 = lds_u32(a0);
                const uint32_t b1 = lds_u32(a0 + (uint32_t)(4 * SXS) * 4);
                mma_f16(acc[0][j], afr[0], b0, b1);
                mma_f16(acc[1][j], afr[1], b0, b1);
                mma_f16(acc[2][j], afr[2], b0, b1);
                mma_f16(acc[3][j], afr[3], b0, b1);
            }
        }
        __syncthreads();
    }

    // ---- epilogue: + scratch, BN, exact GELU ----
#pragma unroll
    for (int nf = 0; nf < 4; nf++) {
#pragma unroll
        for (int half = 0; half < 2; half++) {
            const int ntile = wn * 64 + nf * 16 + (lane >> 2) + half * 8;
            const int n = n0 + ntile;
            const float s = s_s[ntile];
            const float t = s_t[ntile];
#pragma unroll
            for (int j = 0; j < 4; j++) {
                const int m = m0 + wp * 32 + j * 8 + 2 * (lane & 3);
                const unsigned b  = (unsigned)m / HW;
                const unsigned hw = (unsigned)m - b * HW;
                const size_t off = ((size_t)b * NOUT + n) * HW + hw;
                const float2 pre = *reinterpret_cast<const float2*>(g_acc + off);
                float v0 = (acc[nf][j][half * 2 + 0] + pre.x) * s + t;
                float v1 = (acc[nf][j][half * 2 + 1] + pre.y) * s + t;
                v0 = 0.5f * v0 * (1.0f + erff(v0 * 0.70710678118654752440f));
                v1 = 0.5f * v1 * (1.0f + erff(v1 * 0.70710678118654752440f));
                *reinterpret_cast<float2*>(out + off) = make_float2(v0, v1);
            }
        }
    }
}

// ---------------- launch (fork/join: xjpack || gemm_x) ----------------
extern "C" void kernel_launch(void* const* d_in, const int* in_sizes, int n_in,
                              void* d_out, int out_size) {
    const float* x        = (const float*)d_in[0];
    const float* conv_w   = (const float*)d_in[1];
    const float* conv_b   = (const float*)d_in[2];
    const float* bn_scale = (const float*)d_in[3];
    const float* bn_bias  = (const float*)d_in[4];
    const float* bn_mean  = (const float*)d_in[5];
    const float* bn_var   = (const float*)d_in[6];
    float* out = (float*)d_out;

    static cudaStream_t s2 = nullptr;
    static cudaEvent_t evF = nullptr, evJ = nullptr;
    if (s2 == nullptr) {
        cudaStreamCreateWithFlags(&s2, cudaStreamNonBlocking);
        cudaEventCreateWithFlags(&evF, cudaEventDisableTiming);
        cudaEventCreateWithFlags(&evJ, cudaEventDisableTiming);
        cudaFuncSetAttribute(xjpack_kernel,
                             cudaFuncAttributeMaxDynamicSharedMemorySize, XJ_SMEM);
        cudaFuncSetAttribute(gemm_x_kernel,
                             cudaFuncAttributeMaxDynamicSharedMemorySize, SMEM_X);
        cudaFuncSetAttribute(gemm_xj_kernel,
                             cudaFuncAttributeMaxDynamicSharedMemorySize, SMEM_XJ);
    }

    whalf_kernel<<<(NOUT * K0 + 255) / 256, 256>>>(conv_w);
    cudaEventRecord(evF, 0);
    cudaStreamWaitEvent(s2, evF, 0);

    // concurrent: xjpack (legacy) || gemm_x (s2)
    xjpack_kernel<<<B_ * (C_ / 2), dim3(64, 7), XJ_SMEM>>>(x);
    gemm_x_kernel<<<dim3(NOUT / NT, M_ / MT), 256, SMEM_X, s2>>>(x);

    cudaEventRecord(evJ, s2);
    cudaStreamWaitEvent(0, evJ, 0);

    gemm_xj_kernel<<<dim3(NOUT / NT, M_ / MT), 256, SMEM_XJ>>>(
        conv_b, bn_scale, bn_bias, bn_mean, bn_var, out);
}

// round 9
// speedup vs baseline: 1.3136x; 1.3136x over previous
#include <cuda_runtime.h>
#include <cuda_fp16.h>
#include <cstdint>

#define DI __device__ __forceinline__

// ---------------- problem constants ----------------
constexpr int B_   = 16;
constexpr int C_   = 384;
constexpr int H_   = 56;
constexpr int W_   = 56;
constexpr int HW   = H_ * W_;          // 3136
constexpr int M_   = B_ * HW;          // 50176 (pixels)
constexpr int K0   = 2 * C_;           // 768
constexpr int K2T  = K0 / 2;           // 384 packed k-pairs
constexpr int NOUT = 384;

// ---------------- device scratch ----------------
// Xp: packed fp16 pairs, word (k2, m): {fp16(val[2*k2]), fp16(val[2*k2+1])}
// layout [b][k2][hw]; k2 0..191 -> x channel pairs, 192..383 -> xj pairs.
__device__ __align__(256) uint32_t g_Xp[(size_t)B_ * K2T * HW];   // 77 MB
__device__ __align__(256) __half   g_Wh[NOUT * K0];               // fp16 W [n][k]

// ---------------- PTX helpers ----------------
DI uint32_t smem_u32(const void* p) {
    uint32_t a;
    asm("{ .reg .u64 t; cvta.to.shared.u64 t, %1; cvt.u32.u64 %0, t; }"
        : "=r"(a) : "l"(p));
    return a;
}

#define CP_ASYNC16(smem, gptr) \
    asm volatile("cp.async.cg.shared.global [%0], [%1], 16;" :: "r"(smem), "l"(gptr))
#define CP_COMMIT() asm volatile("cp.async.commit_group;")
#define CP_WAIT1()  asm volatile("cp.async.wait_group 1;")
#define CP_WAIT0()  asm volatile("cp.async.wait_group 0;")

DI void ldsm_x4(uint32_t* r, uint32_t addr) {
    asm volatile("ldmatrix.sync.aligned.m8n8.x4.shared.b16 {%0,%1,%2,%3}, [%4];"
                 : "=r"(r[0]), "=r"(r[1]), "=r"(r[2]), "=r"(r[3]) : "r"(addr));
}

DI uint32_t lds_u32(uint32_t addr) {
    uint32_t v;
    asm volatile("ld.shared.b32 %0, [%1];" : "=r"(v) : "r"(addr));
    return v;
}

// D[16 n][8 m] += A[16 n][16 k](f16) * B[16 k][8 m](f16), f32 accum
DI void mma_f16(float* d, const uint32_t* a, uint32_t b0, uint32_t b1) {
    asm volatile(
        "mma.sync.aligned.m16n8k16.row.col.f32.f16.f16.f32 "
        "{%0,%1,%2,%3},{%4,%5,%6,%7},{%8,%9},{%0,%1,%2,%3};"
        : "+f"(d[0]), "+f"(d[1]), "+f"(d[2]), "+f"(d[3])
        : "r"(a[0]), "r"(a[1]), "r"(a[2]), "r"(a[3]), "r"(b0), "r"(b1));
}

DI uint32_t pack_h2(float a, float b) {
    __half2 h = __halves2half2(__float2half_rn(a), __float2half_rn(b));
    return *reinterpret_cast<uint32_t*>(&h);
}

DI __half2 u2h(uint32_t u) { return *reinterpret_cast<__half2*>(&u); }
DI uint32_t h2u(__half2 h) { return *reinterpret_cast<uint32_t*>(&h); }

// ---------------- kernel 1: xjpack (half2 tile, log-shift-max + pack) -------
constexpr int TSTR = 120;
constexpr int XJ_SMEM = 118 * TSTR * 4;             // 56640 B

__global__ void __launch_bounds__(448, 3) xjpack_kernel(const float* __restrict__ x) {
    extern __shared__ uint32_t t[];

    const int c2 = blockIdx.x % (C_ / 2);
    const int b  = blockIdx.x / (C_ / 2);
    const float* src0 = x + ((size_t)b * C_ + 2 * c2    ) * HW;
    const float* src1 = x + ((size_t)b * C_ + 2 * c2 + 1) * HW;

    const int w  = threadIdx.x;                 // 0..63 (>=56 idle)
    const int ty = threadIdx.y;                 // 0..6
    const int hb = ty * 8;

    if (w < W_) {
#pragma unroll
        for (int j = 0; j < 8; j++)
            t[(31 + hb + j) * TSTR + 31 + w] =
                pack_h2(src0[(hb + j) * W_ + w], src1[(hb + j) * W_ + w]);
    }
    __syncthreads();

    if (w < W_) {
#pragma unroll
        for (int r = ty; r < 31; r += 7) {
            t[r * TSTR + 31 + w]        = t[(r + 56) * TSTR + 31 + w];
            t[(r + 87) * TSTR + 31 + w] = t[(r + 31) * TSTR + 31 + w];
        }
    }
    if (w < 31) {
#pragma unroll
        for (int r = 31 + ty; r < 87; r += 7) {
            t[r * TSTR + w]      = t[r * TSTR + w + 56];
            t[r * TSTR + 87 + w] = t[r * TSTR + 31 + w];
        }
    }
    __syncthreads();

    if (w >= W_) return;

    const uint32_t* bp = &t[(31 + hb) * TSTR + 31 + w];
    uint32_t* dx = g_Xp + ((size_t)b * K2T + c2)       * HW + hb * W_ + w;
    uint32_t* dj = g_Xp + ((size_t)b * K2T + 192 + c2) * HW + hb * W_ + w;

    const __half2 zero = __half2half2(__float2half(0.f));

#pragma unroll 2
    for (int j = 0; j < 8; j++) {
        const uint32_t* p = bp + j * TSTR;
        const uint32_t vw = p[0];
        const __half2 v = u2h(vw);

        __half2 m = __hmin2(u2h(p[-1 * TSTR]),  u2h(p[1 * TSTR]));
        m = __hmin2(m, __hmin2(u2h(p[-3 * TSTR]),  u2h(p[3 * TSTR])));
        m = __hmin2(m, __hmin2(u2h(p[-7 * TSTR]),  u2h(p[7 * TSTR])));
        m = __hmin2(m, __hmin2(u2h(p[-15 * TSTR]), u2h(p[15 * TSTR])));
        m = __hmin2(m, __hmin2(u2h(p[-31 * TSTR]), u2h(p[31 * TSTR])));
        m = __hmin2(m, __hmin2(u2h(p[-1]),  u2h(p[1])));
        m = __hmin2(m, __hmin2(u2h(p[-3]),  u2h(p[3])));
        m = __hmin2(m, __hmin2(u2h(p[-7]),  u2h(p[7])));
        m = __hmin2(m, __hmin2(u2h(p[-15]), u2h(p[15])));
        m = __hmin2(m, __hmin2(u2h(p[-31]), u2h(p[31])));

        dx[j * W_] = vw;
        dj[j * W_] = h2u(__hmax2(__hsub2(v, m), zero));
    }
}

// ---------------- kernel 2: W -> fp16 [n][k] ----------------
__global__ void whalf_kernel(const float* __restrict__ w) {
    const int i = blockIdx.x * blockDim.x + threadIdx.x;
    if (i < NOUT * K0) g_Wh[i] = __float2half_rn(w[i]);
}

// ---------------- kernel 3: fp16 mma.sync GEMM + BN + GELU ----------------
// D[n_out][pix]; CTA tile 128n x 128m; K chunks of 32 (16 k2 words).
// Warp tile: 64n x 32m. 3-stage cp.async pipeline, one barrier per chunk.
constexpr int MT  = 128;
constexpr int NT  = 128;
constexpr int KT  = 32;          // k per chunk
constexpr int NCH = K0 / KT;     // 24
constexpr int SXS = 136;         // sX row stride (words), 16 rows/stage
constexpr int SWSH = 40;         // sW row stride (halfs) -> 80B
constexpr int NSTG = 3;
constexpr int SX_STAGE_W = 16 * SXS;          // 2176 words
constexpr int SW_STAGE_H = NT * SWSH;         // 5120 halfs
constexpr int SMEM_BYTES = NSTG * (SX_STAGE_W * 4 + SW_STAGE_H * 2);  // 56832

__global__ void __launch_bounds__(256, 2) gemm_kernel(
    const float* __restrict__ conv_b,
    const float* __restrict__ bn_scale, const float* __restrict__ bn_bias,
    const float* __restrict__ bn_mean,  const float* __restrict__ bn_var,
    float* __restrict__ out)
{
    extern __shared__ uint32_t smw[];
    uint32_t* sX = smw;                               // [3][16][SXS] words
    __half*   sW = (__half*)(smw + NSTG * SX_STAGE_W);// [3][NT][SWSH] halfs
    __shared__ float s_s[NT], s_t[NT];

    const int tid  = threadIdx.x;
    const int lane = tid & 31;
    const int wid  = tid >> 5;
    const int wn   = wid & 1;           // 2 x 64 n
    const int wp   = wid >> 1;          // 4 x 32 m
    const int n0   = blockIdx.x * NT;
    const int m0   = blockIdx.y * MT;

    if (tid < NT) {
        const int n = n0 + tid;
        const float inv = rsqrtf(bn_var[n] + 1e-5f);
        const float s = inv * bn_scale[n];
        s_s[tid] = s;
        s_t[tid] = (conv_b[n] - bn_mean[n]) * s + bn_bias[n];
    }

    const uint32_t sxB = smem_u32(sX);
    const uint32_t swB = smem_u32(sW);

    auto load_chunk = [&](int ch, int st) {
        const int kc2 = ch * (KT / 2);          // k2 offset
        const uint32_t xb = sxB + (uint32_t)st * SX_STAGE_W * 4;
        const uint32_t wb = swB + (uint32_t)st * SW_STAGE_H * 2;
#pragma unroll
        for (int i = 0; i < 2; i++) {
            const int idx = tid + 256 * i;
            const int k2  = idx >> 5;           // 0..15
            const int mv  = idx & 31;           // 16B unit (4 m)
            const int m   = m0 + 4 * mv;
            const unsigned b  = (unsigned)m / HW;
            const unsigned hw = (unsigned)m - b * HW;
            const uint32_t* src = g_Xp + ((size_t)b * K2T + kc2 + k2) * HW + hw;
            CP_ASYNC16(xb + (uint32_t)(k2 * SXS + 4 * mv) * 4, src);
        }
#pragma unroll
        for (int i = 0; i < 2; i++) {
            const int idx = tid + 256 * i;
            const int n   = idx >> 2;           // 0..127
            const int kv  = idx & 3;            // 8-half unit
            const __half* src = g_Wh + (size_t)(n0 + n) * K0 + ch * KT + 8 * kv;
            CP_ASYNC16(wb + (uint32_t)(n * SWSH + 8 * kv) * 2, src);
        }
    };

    float acc[4][4][4];
#pragma unroll
    for (int a = 0; a < 4; a++)
#pragma unroll
        for (int j = 0; j < 4; j++)
#pragma unroll
            for (int q = 0; q < 4; q++) acc[a][j][q] = 0.f;

    // prologue: two chunks in flight
    load_chunk(0, 0);
    CP_COMMIT();
    load_chunk(1, 1);
    CP_COMMIT();

    const int jrow = (lane & 7) + ((lane >> 3) & 1) * 8;
    const int kcol = (lane >> 4) * 8;           // half offset 0 or 8

#pragma unroll 1
    for (int ch = 0; ch < NCH; ch++) {
        if (ch == NCH - 1) { CP_WAIT0(); } else { CP_WAIT1(); }
        __syncthreads();    // stage ch visible to all; stage (ch-1) fully consumed

        if (ch + 2 < NCH) {
            load_chunk(ch + 2, (ch + 2) % NSTG);   // overwrites stage freed at ch-1
            CP_COMMIT();
        }

        const int st = ch % NSTG;
        const uint32_t xb = sxB + (uint32_t)st * SX_STAGE_W * 4;
        const uint32_t wb = swB + (uint32_t)st * SW_STAGE_H * 2;

#pragma unroll
        for (int ks = 0; ks < 2; ks++) {        // two k16 steps
            uint32_t afr[4][4];
#pragma unroll
            for (int nf = 0; nf < 4; nf++) {
                const int row = wn * 64 + nf * 16 + jrow;
                ldsm_x4(afr[nf], wb + (uint32_t)(row * SWSH + ks * 16 + kcol) * 2);
            }
            const uint32_t bbase = xb + (uint32_t)((ks * 8 + (lane & 3)) * SXS
                                                   + wp * 32 + (lane >> 2)) * 4;
            uint32_t bo[8];
#pragma unroll
            for (int j = 0; j < 4; j++) {       // batch all B loads (MLP)
                const uint32_t a0 = bbase + (uint32_t)(j * 8) * 4;
                bo[2 * j]     = lds_u32(a0);
                bo[2 * j + 1] = lds_u32(a0 + (uint32_t)(4 * SXS) * 4);
            }
#pragma unroll
            for (int j = 0; j < 4; j++) {
                mma_f16(acc[0][j], afr[0], bo[2 * j], bo[2 * j + 1]);
                mma_f16(acc[1][j], afr[1], bo[2 * j], bo[2 * j + 1]);
                mma_f16(acc[2][j], afr[2], bo[2 * j], bo[2 * j + 1]);
                mma_f16(acc[3][j], afr[3], bo[2 * j], bo[2 * j + 1]);
            }
        }
    }

    // ---- epilogue: BN + exact GELU ----
#pragma unroll
    for (int nf = 0; nf < 4; nf++) {
#pragma unroll
        for (int half = 0; half < 2; half++) {
            const int ntile = wn * 64 + nf * 16 + (lane >> 2) + half * 8;
            const int n = n0 + ntile;
            const float s = s_s[ntile];
            const float t = s_t[ntile];
#pragma unroll
            for (int j = 0; j < 4; j++) {
                const int m = m0 + wp * 32 + j * 8 + 2 * (lane & 3);
                const unsigned b  = (unsigned)m / HW;
                const unsigned hw = (unsigned)m - b * HW;
                float v0 = acc[nf][j][half * 2 + 0] * s + t;
                float v1 = acc[nf][j][half * 2 + 1] * s + t;
                v0 = 0.5f * v0 * (1.0f + erff(v0 * 0.70710678118654752440f));
                v1 = 0.5f * v1 * (1.0f + erff(v1 * 0.70710678118654752440f));
                *reinterpret_cast<float2*>(
                    out + ((size_t)b * NOUT + n) * HW + hw) = make_float2(v0, v1);
            }
        }
    }
}

// ---------------- launch ----------------
extern "C" void kernel_launch(void* const* d_in, const int* in_sizes, int n_in,
                              void* d_out, int out_size) {
    const float* x        = (const float*)d_in[0];
    const float* conv_w   = (const float*)d_in[1];
    const float* conv_b   = (const float*)d_in[2];
    const float* bn_scale = (const float*)d_in[3];
    const float* bn_bias  = (const float*)d_in[4];
    const float* bn_mean  = (const float*)d_in[5];
    const float* bn_var   = (const float*)d_in[6];
    float* out = (float*)d_out;

    cudaFuncSetAttribute(xjpack_kernel,
                         cudaFuncAttributeMaxDynamicSharedMemorySize, XJ_SMEM);
    cudaFuncSetAttribute(gemm_kernel,
                         cudaFuncAttributeMaxDynamicSharedMemorySize, SMEM_BYTES);

    xjpack_kernel<<<B_ * (C_ / 2), dim3(64, 7), XJ_SMEM>>>(x);
    whalf_kernel<<<(NOUT * K0 + 255) / 256, 256>>>(conv_w);
    gemm_kernel<<<dim3(NOUT / NT, M_ / MT), 256, SMEM_BYTES>>>(
        conv_b, bn_scale, bn_bias, bn_mean, bn_var, out);
}